// round 1
// baseline (speedup 1.0000x reference)
#include <cuda_runtime.h>
#include <cstdint>

#define T_STEPS 4096
#define HD      512
#define NC      4880
#define G3      1536

// ---------------- scratch (device globals: no runtime allocation) ------------
__device__ float    g_visit[(size_t)T_STEPS * HD];    // 8 MB
__device__ float    g_gi[(size_t)T_STEPS * G3];       // 25 MB
__device__ float    g_hs[(size_t)T_STEPS * HD];       // 8 MB
__device__ float    g_logits[T_STEPS];
__device__ float    g_alpha[T_STEPS];
__device__ unsigned g_cnt[T_STEPS];

// ---------------- K0: zero the per-step arrival counters ---------------------
__global__ void k_zero() {
    int i = blockIdx.x * blockDim.x + threadIdx.x;
    if (i < T_STEPS) g_cnt[i] = 0u;
}

// ---------------- K1: visit_emb[t][j] = sum_c H[c][t] * X[c][j] --------------
// H: (4880, 4096) row-major; X: (4880, 512) row-major. Tiles 128(t) x 64(j), BK=16.
__global__ __launch_bounds__(256) void k_gemm1(const float* __restrict__ H,
                                               const float* __restrict__ X) {
    __shared__ float As[16][128];
    __shared__ float Bs[16][64];
    const int t0 = blockIdx.x * 128, j0 = blockIdx.y * 64;
    const int tid = threadIdx.x;
    const int tx = tid & 15, ty = tid >> 4;

    float acc[8][4];
#pragma unroll
    for (int m = 0; m < 8; m++)
#pragma unroll
        for (int n = 0; n < 4; n++) acc[m][n] = 0.f;

    for (int c0 = 0; c0 < NC; c0 += 16) {
#pragma unroll
        for (int i = 0; i < 2; i++) {
            int idx = tid + i * 256;
            int r = idx >> 5, c4 = (idx & 31) << 2;
            *(float4*)&As[r][c4] =
                *(const float4*)&H[(size_t)(c0 + r) * T_STEPS + t0 + c4];
        }
        {
            int r = tid >> 4, c4 = (tid & 15) << 2;
            *(float4*)&Bs[r][c4] =
                *(const float4*)&X[(size_t)(c0 + r) * HD + j0 + c4];
        }
        __syncthreads();
#pragma unroll
        for (int kk = 0; kk < 16; kk++) {
            float4 a0 = *(float4*)&As[kk][ty * 8];
            float4 a1 = *(float4*)&As[kk][ty * 8 + 4];
            float4 b  = *(float4*)&Bs[kk][tx * 4];
            float a[8] = {a0.x, a0.y, a0.z, a0.w, a1.x, a1.y, a1.z, a1.w};
            float bb[4] = {b.x, b.y, b.z, b.w};
#pragma unroll
            for (int m = 0; m < 8; m++)
#pragma unroll
                for (int n = 0; n < 4; n++) acc[m][n] += a[m] * bb[n];
        }
        __syncthreads();
    }
#pragma unroll
    for (int m = 0; m < 8; m++) {
        float4 v = make_float4(acc[m][0], acc[m][1], acc[m][2], acc[m][3]);
        *(float4*)&g_visit[(size_t)(t0 + ty * 8 + m) * HD + j0 + tx * 4] = v;
    }
}

// ---------------- K2: gi[t][g] = sum_k visit[t][k] * W_ih[g][k] + b_ih[g] ----
// Tiles 128(t) x 64(g), BK=32; both operands k-contiguous -> transpose on store.
__global__ __launch_bounds__(256) void k_gemm2(const float* __restrict__ W_ih,
                                               const float* __restrict__ b_ih) {
    __shared__ float As[32][129];   // As[k][t], padded
    __shared__ float Bs[32][64];    // Bs[k][g]
    const int t0 = blockIdx.x * 128, g0 = blockIdx.y * 64;
    const int tid = threadIdx.x;
    const int tx = tid & 15, ty = tid >> 4;

    float acc[8][4];
#pragma unroll
    for (int m = 0; m < 8; m++)
#pragma unroll
        for (int n = 0; n < 4; n++) acc[m][n] = 0.f;

    for (int k0 = 0; k0 < HD; k0 += 32) {
        {
            int t_l = tid >> 1;
#pragma unroll
            for (int i = 0; i < 4; i++) {
                int q = (tid & 1) + i * 2;   // 0..7
                float4 v = *(const float4*)&g_visit[(size_t)(t0 + t_l) * HD + k0 + q * 4];
                As[q * 4 + 0][t_l] = v.x; As[q * 4 + 1][t_l] = v.y;
                As[q * 4 + 2][t_l] = v.z; As[q * 4 + 3][t_l] = v.w;
            }
        }
        {
            int g_l = tid >> 2;
#pragma unroll
            for (int i = 0; i < 2; i++) {
                int q = (tid & 3) + i * 4;   // 0..7
                float4 w = *(const float4*)&W_ih[(size_t)(g0 + g_l) * HD + k0 + q * 4];
                Bs[q * 4 + 0][g_l] = w.x; Bs[q * 4 + 1][g_l] = w.y;
                Bs[q * 4 + 2][g_l] = w.z; Bs[q * 4 + 3][g_l] = w.w;
            }
        }
        __syncthreads();
#pragma unroll
        for (int kk = 0; kk < 32; kk++) {
            float a[8];
#pragma unroll
            for (int m = 0; m < 8; m++) a[m] = As[kk][ty * 8 + m];
            float4 b = *(float4*)&Bs[kk][tx * 4];
            float bb[4] = {b.x, b.y, b.z, b.w};
#pragma unroll
            for (int m = 0; m < 8; m++)
#pragma unroll
                for (int n = 0; n < 4; n++) acc[m][n] += a[m] * bb[n];
        }
        __syncthreads();
    }
    float4 bias = *(const float4*)&b_ih[g0 + tx * 4];
    float bb[4] = {bias.x, bias.y, bias.z, bias.w};
#pragma unroll
    for (int m = 0; m < 8; m++) {
        float4 v = make_float4(acc[m][0] + bb[0], acc[m][1] + bb[1],
                               acc[m][2] + bb[2], acc[m][3] + bb[3]);
        *(float4*)&g_gi[(size_t)(t0 + ty * 8 + m) * G3 + g0 + tx * 4] = v;
    }
}

// ---------------- K3: persistent GRU scan ------------------------------------
// 128 CTAs x 128 threads. Warp w of CTA b owns hidden unit j = b*4 + w.
// W_hh rows (r,z,n for j) live in registers. Per-step chip-wide sync through
// per-step counters in L2 (release/acquire).
__global__ __launch_bounds__(128) void k_scan(const float* __restrict__ Whh,
                                              const float* __restrict__ bhh) {
    const int warp = threadIdx.x >> 5, lane = threadIdx.x & 31;
    const int j = blockIdx.x * 4 + warp;

    float4 wr[4], wz[4], wn[4];
#pragma unroll
    for (int i = 0; i < 4; i++) {
        wr[i] = *(const float4*)&Whh[(size_t)j * HD          + lane * 16 + i * 4];
        wz[i] = *(const float4*)&Whh[(size_t)(512  + j) * HD + lane * 16 + i * 4];
        wn[i] = *(const float4*)&Whh[(size_t)(1024 + j) * HD + lane * 16 + i * 4];
    }
    const float br = bhh[j], bz = bhh[512 + j], bn = bhh[1024 + j];
    float h_prev = 0.f;

    for (int t = 0; t < T_STEPS; t++) {
        // prefetch gate inputs (independent of h)
        const float* gp = &g_gi[(size_t)t * G3];
        float ir  = __ldg(gp + j);
        float iz  = __ldg(gp + 512 + j);
        float in_ = __ldg(gp + 1024 + j);

        if (t > 0) {
            if (threadIdx.x == 0) {
                unsigned v;
                do {
                    asm volatile("ld.acquire.gpu.global.u32 %0, [%1];"
                                 : "=r"(v) : "l"(&g_cnt[t - 1]) : "memory");
                } while (v < 512u);
            }
            __syncthreads();
        }

        float accr = 0.f, accz = 0.f, accn = 0.f;
        if (t > 0) {
            const float4* hp = (const float4*)&g_hs[(size_t)(t - 1) * HD + lane * 16];
#pragma unroll
            for (int i = 0; i < 4; i++) {
                float4 h4 = __ldcg(hp + i);
                accr += wr[i].x * h4.x + wr[i].y * h4.y + wr[i].z * h4.z + wr[i].w * h4.w;
                accz += wz[i].x * h4.x + wz[i].y * h4.y + wz[i].z * h4.z + wz[i].w * h4.w;
                accn += wn[i].x * h4.x + wn[i].y * h4.y + wn[i].z * h4.z + wn[i].w * h4.w;
            }
        }
#pragma unroll
        for (int off = 16; off > 0; off >>= 1) {
            accr += __shfl_xor_sync(0xffffffffu, accr, off);
            accz += __shfl_xor_sync(0xffffffffu, accz, off);
            accn += __shfl_xor_sync(0xffffffffu, accn, off);
        }
        float r = 1.f / (1.f + __expf(-(ir + accr + br)));
        float z = 1.f / (1.f + __expf(-(iz + accz + bz)));
        float n = tanhf(in_ + r * (accn + bn));
        float hn = (1.f - z) * n + z * h_prev;
        h_prev = hn;

        if (lane == 0) {
            g_hs[(size_t)t * HD + j] = hn;
            asm volatile("red.release.gpu.global.add.u32 [%0], %1;"
                         :: "l"(&g_cnt[t]), "r"(1u) : "memory");
        }
    }
}

// ---------------- K4a: logits[t] = dot(hs[t], w_att) -------------------------
__global__ __launch_bounds__(256) void k_logits(const float* __restrict__ watt) {
    const int warp = threadIdx.x >> 5, lane = threadIdx.x & 31;
    const int t = blockIdx.x * 8 + warp;
    float acc = 0.f;
#pragma unroll
    for (int i = 0; i < 4; i++) {
        float4 h4 = *(const float4*)&g_hs[(size_t)t * HD + lane * 16 + i * 4];
        float4 w4 = *(const float4*)&watt[lane * 16 + i * 4];
        acc += h4.x * w4.x + h4.y * w4.y + h4.z * w4.z + h4.w * w4.w;
    }
#pragma unroll
    for (int off = 16; off > 0; off >>= 1)
        acc += __shfl_xor_sync(0xffffffffu, acc, off);
    if (lane == 0) g_logits[t] = acc;
}

// ---------------- K4b: softmax over 4096 logits ------------------------------
__global__ __launch_bounds__(1024) void k_softmax() {
    __shared__ float red[1024];
    const int tid = threadIdx.x;
    float l[4];
    float m = -3.4e38f;
#pragma unroll
    for (int i = 0; i < 4; i++) {
        l[i] = g_logits[tid + i * 1024];
        m = fmaxf(m, l[i]);
    }
    red[tid] = m;
    __syncthreads();
    for (int s = 512; s > 0; s >>= 1) {
        if (tid < s) red[tid] = fmaxf(red[tid], red[tid + s]);
        __syncthreads();
    }
    const float M = red[0];
    __syncthreads();
    float e[4];
    float sum = 0.f;
#pragma unroll
    for (int i = 0; i < 4; i++) {
        e[i] = __expf(l[i] - M);
        sum += e[i];
    }
    red[tid] = sum;
    __syncthreads();
    for (int s = 512; s > 0; s >>= 1) {
        if (tid < s) red[tid] += red[tid + s];
        __syncthreads();
    }
    const float inv = 1.f / red[0];
#pragma unroll
    for (int i = 0; i < 4; i++) g_alpha[tid + i * 1024] = e[i] * inv;
}

// ---------------- K4c: out[j] = sum_t alpha[t] * hs[t][j] --------------------
__global__ __launch_bounds__(128) void k_out(float* __restrict__ out) {
    __shared__ float al[T_STEPS];
    const int j = blockIdx.x * 128 + threadIdx.x;
    for (int i = threadIdx.x; i < T_STEPS; i += 128) al[i] = g_alpha[i];
    __syncthreads();
    float acc = 0.f;
#pragma unroll 8
    for (int t = 0; t < T_STEPS; t++)
        acc += al[t] * g_hs[(size_t)t * HD + j];
    out[j] = acc;
}

// ---------------- launch ------------------------------------------------------
extern "C" void kernel_launch(void* const* d_in, const int* in_sizes, int n_in,
                              void* d_out, int out_size) {
    const float* H     = (const float*)d_in[0];
    // d_in[1] = TE (unused)
    const float* X     = (const float*)d_in[2];
    const float* W_ih  = (const float*)d_in[3];
    const float* W_hh  = (const float*)d_in[4];
    const float* b_ih  = (const float*)d_in[5];
    const float* b_hh  = (const float*)d_in[6];
    const float* w_att = (const float*)d_in[7];
    float* out = (float*)d_out;

    k_zero<<<4, 1024>>>();
    k_gemm1<<<dim3(32, 8), 256>>>(H, X);
    k_gemm2<<<dim3(32, 24), 256>>>(W_ih, b_ih);
    k_scan<<<128, 128>>>(W_hh, b_hh);
    k_logits<<<512, 256>>>(w_att);
    k_softmax<<<1, 1024>>>();
    k_out<<<4, 128>>>(out);
}

// round 4
// speedup vs baseline: 1.0508x; 1.0508x over previous
#include <cuda_runtime.h>
#include <cstdint>

#define T_STEPS 4096
#define HD      512
#define NC      4880
#define G3      1536
#define SCAN_CTAS 32
#define SCAN_WARPS 16   // warps per CTA; SCAN_CTAS*SCAN_WARPS == 512 units

// ---------------- scratch (device globals: no runtime allocation) ------------
__device__ float    g_visit[(size_t)T_STEPS * HD];    // 8 MB
__device__ float    g_gi[(size_t)T_STEPS * G3];       // 25 MB
__device__ float    g_hs[(size_t)T_STEPS * HD];       // 8 MB
__device__ float    g_logits[T_STEPS];
__device__ float    g_alpha[T_STEPS];
__device__ unsigned g_cnt[T_STEPS];

// ---------------- K0: zero the per-step arrival counters ---------------------
__global__ void k_zero() {
    int i = blockIdx.x * blockDim.x + threadIdx.x;
    if (i < T_STEPS) g_cnt[i] = 0u;
}

// ---------------- K1: visit_emb[t][j] = sum_c H[c][t] * X[c][j] --------------
__global__ __launch_bounds__(256) void k_gemm1(const float* __restrict__ H,
                                               const float* __restrict__ X) {
    __shared__ float As[16][128];
    __shared__ float Bs[16][64];
    const int t0 = blockIdx.x * 128, j0 = blockIdx.y * 64;
    const int tid = threadIdx.x;
    const int tx = tid & 15, ty = tid >> 4;

    float acc[8][4];
#pragma unroll
    for (int m = 0; m < 8; m++)
#pragma unroll
        for (int n = 0; n < 4; n++) acc[m][n] = 0.f;

    for (int c0 = 0; c0 < NC; c0 += 16) {
#pragma unroll
        for (int i = 0; i < 2; i++) {
            int idx = tid + i * 256;
            int r = idx >> 5, c4 = (idx & 31) << 2;
            *(float4*)&As[r][c4] =
                *(const float4*)&H[(size_t)(c0 + r) * T_STEPS + t0 + c4];
        }
        {
            int r = tid >> 4, c4 = (tid & 15) << 2;
            *(float4*)&Bs[r][c4] =
                *(const float4*)&X[(size_t)(c0 + r) * HD + j0 + c4];
        }
        __syncthreads();
#pragma unroll
        for (int kk = 0; kk < 16; kk++) {
            float4 a0 = *(float4*)&As[kk][ty * 8];
            float4 a1 = *(float4*)&As[kk][ty * 8 + 4];
            float4 b  = *(float4*)&Bs[kk][tx * 4];
            float a[8] = {a0.x, a0.y, a0.z, a0.w, a1.x, a1.y, a1.z, a1.w};
            float bb[4] = {b.x, b.y, b.z, b.w};
#pragma unroll
            for (int m = 0; m < 8; m++)
#pragma unroll
                for (int n = 0; n < 4; n++) acc[m][n] += a[m] * bb[n];
        }
        __syncthreads();
    }
#pragma unroll
    for (int m = 0; m < 8; m++) {
        float4 v = make_float4(acc[m][0], acc[m][1], acc[m][2], acc[m][3]);
        *(float4*)&g_visit[(size_t)(t0 + ty * 8 + m) * HD + j0 + tx * 4] = v;
    }
}

// ---------------- K2: gi[t][g] = sum_k visit[t][k] * W_ih[g][k] + b_ih[g] ----
__global__ __launch_bounds__(256) void k_gemm2(const float* __restrict__ W_ih,
                                               const float* __restrict__ b_ih) {
    __shared__ float As[32][129];   // As[k][t], padded
    __shared__ float Bs[32][64];    // Bs[k][g]
    const int t0 = blockIdx.x * 128, g0 = blockIdx.y * 64;
    const int tid = threadIdx.x;
    const int tx = tid & 15, ty = tid >> 4;

    float acc[8][4];
#pragma unroll
    for (int m = 0; m < 8; m++)
#pragma unroll
        for (int n = 0; n < 4; n++) acc[m][n] = 0.f;

    for (int k0 = 0; k0 < HD; k0 += 32) {
        {
            int t_l = tid >> 1;
#pragma unroll
            for (int i = 0; i < 4; i++) {
                int q = (tid & 1) + i * 2;   // 0..7
                float4 v = *(const float4*)&g_visit[(size_t)(t0 + t_l) * HD + k0 + q * 4];
                As[q * 4 + 0][t_l] = v.x; As[q * 4 + 1][t_l] = v.y;
                As[q * 4 + 2][t_l] = v.z; As[q * 4 + 3][t_l] = v.w;
            }
        }
        {
            int g_l = tid >> 2;
#pragma unroll
            for (int i = 0; i < 2; i++) {
                int q = (tid & 3) + i * 4;   // 0..7
                float4 w = *(const float4*)&W_ih[(size_t)(g0 + g_l) * HD + k0 + q * 4];
                Bs[q * 4 + 0][g_l] = w.x; Bs[q * 4 + 1][g_l] = w.y;
                Bs[q * 4 + 2][g_l] = w.z; Bs[q * 4 + 3][g_l] = w.w;
            }
        }
        __syncthreads();
#pragma unroll
        for (int kk = 0; kk < 32; kk++) {
            float a[8];
#pragma unroll
            for (int m = 0; m < 8; m++) a[m] = As[kk][ty * 8 + m];
            float4 b = *(float4*)&Bs[kk][tx * 4];
            float bb[4] = {b.x, b.y, b.z, b.w};
#pragma unroll
            for (int m = 0; m < 8; m++)
#pragma unroll
                for (int n = 0; n < 4; n++) acc[m][n] += a[m] * bb[n];
        }
        __syncthreads();
    }
    float4 bias = *(const float4*)&b_ih[g0 + tx * 4];
    float bb[4] = {bias.x, bias.y, bias.z, bias.w};
#pragma unroll
    for (int m = 0; m < 8; m++) {
        float4 v = make_float4(acc[m][0] + bb[0], acc[m][1] + bb[1],
                               acc[m][2] + bb[2], acc[m][3] + bb[3]);
        *(float4*)&g_gi[(size_t)(t0 + ty * 8 + m) * G3 + g0 + tx * 4] = v;
    }
}

// ---------------- K3: persistent GRU scan ------------------------------------
// 32 CTAs x 512 threads (16 warps). Warp w of CTA b owns hidden unit
// j = b*16 + w. W_hh rows (r,z,n) in registers. Per step: hierarchical
// arrival -- warps deposit h in SMEM, one coalesced 64B store, ONE
// red.release.gpu.add per CTA (32 single-address atomics/step, not 512).
__global__ __launch_bounds__(512) void k_scan(const float* __restrict__ Whh,
                                              const float* __restrict__ bhh) {
    __shared__ float sh_h[SCAN_WARPS];
    const int warp = threadIdx.x >> 5, lane = threadIdx.x & 31;
    const int j = blockIdx.x * SCAN_WARPS + warp;

    float4 wr[4], wz[4], wn[4];
#pragma unroll
    for (int i = 0; i < 4; i++) {
        wr[i] = *(const float4*)&Whh[(size_t)j * HD          + lane * 16 + i * 4];
        wz[i] = *(const float4*)&Whh[(size_t)(512  + j) * HD + lane * 16 + i * 4];
        wn[i] = *(const float4*)&Whh[(size_t)(1024 + j) * HD + lane * 16 + i * 4];
    }
    const float br = bhh[j], bz = bhh[512 + j], bn = bhh[1024 + j];
    float h_prev = 0.f;

    for (int t = 0; t < T_STEPS; t++) {
        // prefetch gate inputs (independent of h)
        const float* gp = &g_gi[(size_t)t * G3];
        float ir  = __ldg(gp + j);
        float iz  = __ldg(gp + 512 + j);
        float in_ = __ldg(gp + 1024 + j);

        float accr = 0.f, accz = 0.f, accn = 0.f;
        if (t > 0) {
            if (threadIdx.x == 0) {
                unsigned v;
                do {
                    asm volatile("ld.acquire.gpu.global.u32 %0, [%1];"
                                 : "=r"(v) : "l"(&g_cnt[t - 1]) : "memory");
                } while (v < (unsigned)SCAN_CTAS);
            }
            __syncthreads();

            const float4* hp = (const float4*)&g_hs[(size_t)(t - 1) * HD + lane * 16];
#pragma unroll
            for (int i = 0; i < 4; i++) {
                float4 h4 = __ldcg(hp + i);
                accr += wr[i].x * h4.x + wr[i].y * h4.y + wr[i].z * h4.z + wr[i].w * h4.w;
                accz += wz[i].x * h4.x + wz[i].y * h4.y + wz[i].z * h4.z + wz[i].w * h4.w;
                accn += wn[i].x * h4.x + wn[i].y * h4.y + wn[i].z * h4.z + wn[i].w * h4.w;
            }
        }
#pragma unroll
        for (int off = 16; off > 0; off >>= 1) {
            accr += __shfl_xor_sync(0xffffffffu, accr, off);
            accz += __shfl_xor_sync(0xffffffffu, accz, off);
            accn += __shfl_xor_sync(0xffffffffu, accn, off);
        }
        float r = 1.f / (1.f + __expf(-(ir + accr + br)));
        float z = 1.f / (1.f + __expf(-(iz + accz + bz)));
        float n = tanhf(in_ + r * (accn + bn));
        float hn = (1.f - z) * n + z * h_prev;
        h_prev = hn;

        if (lane == 0) sh_h[warp] = hn;
        __syncthreads();
        if (threadIdx.x < SCAN_WARPS) {
            // one coalesced 64B segment per CTA
            g_hs[(size_t)t * HD + blockIdx.x * SCAN_WARPS + threadIdx.x] = sh_h[threadIdx.x];
        }
        if (warp == 0) {
            __syncwarp();
            if (lane == 0) {
                asm volatile("red.release.gpu.global.add.u32 [%0], %1;"
                             :: "l"(&g_cnt[t]), "r"(1u) : "memory");
            }
        }
    }
}

// ---------------- K4a: logits[t] = dot(hs[t], w_att) -------------------------
__global__ __launch_bounds__(256) void k_logits(const float* __restrict__ watt) {
    const int warp = threadIdx.x >> 5, lane = threadIdx.x & 31;
    const int t = blockIdx.x * 8 + warp;
    float acc = 0.f;
#pragma unroll
    for (int i = 0; i < 4; i++) {
        float4 h4 = *(const float4*)&g_hs[(size_t)t * HD + lane * 16 + i * 4];
        float4 w4 = *(const float4*)&watt[lane * 16 + i * 4];
        acc += h4.x * w4.x + h4.y * w4.y + h4.z * w4.z + h4.w * w4.w;
    }
#pragma unroll
    for (int off = 16; off > 0; off >>= 1)
        acc += __shfl_xor_sync(0xffffffffu, acc, off);
    if (lane == 0) g_logits[t] = acc;
}

// ---------------- K4b: softmax over 4096 logits ------------------------------
__global__ __launch_bounds__(1024) void k_softmax() {
    __shared__ float red[1024];
    const int tid = threadIdx.x;
    float l[4];
    float m = -3.4e38f;
#pragma unroll
    for (int i = 0; i < 4; i++) {
        l[i] = g_logits[tid + i * 1024];
        m = fmaxf(m, l[i]);
    }
    red[tid] = m;
    __syncthreads();
    for (int s = 512; s > 0; s >>= 1) {
        if (tid < s) red[tid] = fmaxf(red[tid], red[tid + s]);
        __syncthreads();
    }
    const float M = red[0];
    __syncthreads();
    float e[4];
    float sum = 0.f;
#pragma unroll
    for (int i = 0; i < 4; i++) {
        e[i] = __expf(l[i] - M);
        sum += e[i];
    }
    red[tid] = sum;
    __syncthreads();
    for (int s = 512; s > 0; s >>= 1) {
        if (tid < s) red[tid] += red[tid + s];
        __syncthreads();
    }
    const float inv = 1.f / red[0];
#pragma unroll
    for (int i = 0; i < 4; i++) g_alpha[tid + i * 1024] = e[i] * inv;
}

// ---------------- K4c: out[j] = sum_t alpha[t] * hs[t][j] --------------------
__global__ __launch_bounds__(128) void k_out(float* __restrict__ out) {
    __shared__ float al[T_STEPS];
    const int j = blockIdx.x * 128 + threadIdx.x;
    for (int i = threadIdx.x; i < T_STEPS; i += 128) al[i] = g_alpha[i];
    __syncthreads();
    float acc = 0.f;
#pragma unroll 8
    for (int t = 0; t < T_STEPS; t++)
        acc += al[t] * g_hs[(size_t)t * HD + j];
    out[j] = acc;
}

// ---------------- launch ------------------------------------------------------
extern "C" void kernel_launch(void* const* d_in, const int* in_sizes, int n_in,
                              void* d_out, int out_size) {
    const float* H     = (const float*)d_in[0];
    // d_in[1] = TE (unused)
    const float* X     = (const float*)d_in[2];
    const float* W_ih  = (const float*)d_in[3];
    const float* W_hh  = (const float*)d_in[4];
    const float* b_ih  = (const float*)d_in[5];
    const float* b_hh  = (const float*)d_in[6];
    const float* w_att = (const float*)d_in[7];
    float* out = (float*)d_out;

    k_zero<<<4, 1024>>>();
    k_gemm1<<<dim3(32, 8), 256>>>(H, X);
    k_gemm2<<<dim3(32, 24), 256>>>(W_ih, b_ih);
    k_scan<<<SCAN_CTAS, 512>>>(W_hh, b_hh);
    k_logits<<<512, 256>>>(w_att);
    k_softmax<<<1, 1024>>>();
    k_out<<<4, 128>>>(out);
}

// round 5
// speedup vs baseline: 1.3864x; 1.3193x over previous
#include <cuda_runtime.h>
#include <cstdint>

#define T_STEPS 4096
#define HD      512
#define NC      4880
#define G3      1536
#define SCAN_CTAS 32
#define SCAN_WARPS 16   // warps per CTA; SCAN_CTAS*SCAN_WARPS == 512 units

// ---------------- scratch (device globals: no runtime allocation) ------------
__device__ float    g_visit[(size_t)T_STEPS * HD];    // 8 MB
__device__ float    g_gi[(size_t)T_STEPS * G3];       // 25 MB
__device__ float    g_hs[(size_t)T_STEPS * HD];       // 8 MB
__device__ float    g_logits[T_STEPS];
__device__ float    g_alpha[T_STEPS];
__device__ unsigned g_cnt[T_STEPS];

// ---------------- K0: zero the per-step arrival counters ---------------------
__global__ void k_zero() {
    int i = blockIdx.x * blockDim.x + threadIdx.x;
    if (i < T_STEPS) g_cnt[i] = 0u;
}

// ---------------- K1: visit_emb[t][j] = sum_c H[c][t] * X[c][j] --------------
__global__ __launch_bounds__(256) void k_gemm1(const float* __restrict__ H,
                                               const float* __restrict__ X) {
    __shared__ float As[16][128];
    __shared__ float Bs[16][64];
    const int t0 = blockIdx.x * 128, j0 = blockIdx.y * 64;
    const int tid = threadIdx.x;
    const int tx = tid & 15, ty = tid >> 4;

    float acc[8][4];
#pragma unroll
    for (int m = 0; m < 8; m++)
#pragma unroll
        for (int n = 0; n < 4; n++) acc[m][n] = 0.f;

    for (int c0 = 0; c0 < NC; c0 += 16) {
#pragma unroll
        for (int i = 0; i < 2; i++) {
            int idx = tid + i * 256;
            int r = idx >> 5, c4 = (idx & 31) << 2;
            *(float4*)&As[r][c4] =
                *(const float4*)&H[(size_t)(c0 + r) * T_STEPS + t0 + c4];
        }
        {
            int r = tid >> 4, c4 = (tid & 15) << 2;
            *(float4*)&Bs[r][c4] =
                *(const float4*)&X[(size_t)(c0 + r) * HD + j0 + c4];
        }
        __syncthreads();
#pragma unroll
        for (int kk = 0; kk < 16; kk++) {
            float4 a0 = *(float4*)&As[kk][ty * 8];
            float4 a1 = *(float4*)&As[kk][ty * 8 + 4];
            float4 b  = *(float4*)&Bs[kk][tx * 4];
            float a[8] = {a0.x, a0.y, a0.z, a0.w, a1.x, a1.y, a1.z, a1.w};
            float bb[4] = {b.x, b.y, b.z, b.w};
#pragma unroll
            for (int m = 0; m < 8; m++)
#pragma unroll
                for (int n = 0; n < 4; n++) acc[m][n] += a[m] * bb[n];
        }
        __syncthreads();
    }
#pragma unroll
    for (int m = 0; m < 8; m++) {
        float4 v = make_float4(acc[m][0], acc[m][1], acc[m][2], acc[m][3]);
        *(float4*)&g_visit[(size_t)(t0 + ty * 8 + m) * HD + j0 + tx * 4] = v;
    }
}

// ---------------- K2: gi[t][g] = sum_k visit[t][k] * W_ih[g][k] + b_ih[g] ----
__global__ __launch_bounds__(256) void k_gemm2(const float* __restrict__ W_ih,
                                               const float* __restrict__ b_ih) {
    __shared__ float As[32][129];   // As[k][t], padded
    __shared__ float Bs[32][64];    // Bs[k][g]
    const int t0 = blockIdx.x * 128, g0 = blockIdx.y * 64;
    const int tid = threadIdx.x;
    const int tx = tid & 15, ty = tid >> 4;

    float acc[8][4];
#pragma unroll
    for (int m = 0; m < 8; m++)
#pragma unroll
        for (int n = 0; n < 4; n++) acc[m][n] = 0.f;

    for (int k0 = 0; k0 < HD; k0 += 32) {
        {
            int t_l = tid >> 1;
#pragma unroll
            for (int i = 0; i < 4; i++) {
                int q = (tid & 1) + i * 2;   // 0..7
                float4 v = *(const float4*)&g_visit[(size_t)(t0 + t_l) * HD + k0 + q * 4];
                As[q * 4 + 0][t_l] = v.x; As[q * 4 + 1][t_l] = v.y;
                As[q * 4 + 2][t_l] = v.z; As[q * 4 + 3][t_l] = v.w;
            }
        }
        {
            int g_l = tid >> 2;
#pragma unroll
            for (int i = 0; i < 2; i++) {
                int q = (tid & 3) + i * 4;   // 0..7
                float4 w = *(const float4*)&W_ih[(size_t)(g0 + g_l) * HD + k0 + q * 4];
                Bs[q * 4 + 0][g_l] = w.x; Bs[q * 4 + 1][g_l] = w.y;
                Bs[q * 4 + 2][g_l] = w.z; Bs[q * 4 + 3][g_l] = w.w;
            }
        }
        __syncthreads();
#pragma unroll
        for (int kk = 0; kk < 32; kk++) {
            float a[8];
#pragma unroll
            for (int m = 0; m < 8; m++) a[m] = As[kk][ty * 8 + m];
            float4 b = *(float4*)&Bs[kk][tx * 4];
            float bb[4] = {b.x, b.y, b.z, b.w};
#pragma unroll
            for (int m = 0; m < 8; m++)
#pragma unroll
                for (int n = 0; n < 4; n++) acc[m][n] += a[m] * bb[n];
        }
        __syncthreads();
    }
    float4 bias = *(const float4*)&b_ih[g0 + tx * 4];
    float bb[4] = {bias.x, bias.y, bias.z, bias.w};
#pragma unroll
    for (int m = 0; m < 8; m++) {
        float4 v = make_float4(acc[m][0] + bb[0], acc[m][1] + bb[1],
                               acc[m][2] + bb[2], acc[m][3] + bb[3]);
        *(float4*)&g_gi[(size_t)(t0 + ty * 8 + m) * G3 + g0 + tx * 4] = v;
    }
}

// ---------------- K3: persistent GRU scan ------------------------------------
// 32 CTAs x 512 threads (16 warps). Warp w of CTA b owns hidden unit
// j = b*16 + w; W_hh rows (r,z,n) live in registers.
// Per step:
//   * thread 0 polls per-step counter (acquire), bar
//   * ALL 512 threads fetch h(t-1) ONCE per CTA into SMEM (coalesced 4B .cg
//     loads -> 16 L2 line-requests per SM instead of 256; kills the 512-way
//     per-slice L2 broadcast serialization)
//   * warps compute gates from SMEM h, butterfly-reduce, gate math
//   * publish: SMEM stage -> one coalesced 64B STG -> ONE red.release per CTA
__global__ __launch_bounds__(512) void k_scan(const float* __restrict__ Whh,
                                              const float* __restrict__ bhh) {
    __shared__ float sh_hin[HD];       // staged h(t-1), full vector
    __shared__ float sh_h[SCAN_WARPS]; // this CTA's new h segment
    const int tid = threadIdx.x;
    const int warp = tid >> 5, lane = tid & 31;
    const int j = blockIdx.x * SCAN_WARPS + warp;

    float4 wr[4], wz[4], wn[4];
#pragma unroll
    for (int i = 0; i < 4; i++) {
        wr[i] = *(const float4*)&Whh[(size_t)j * HD          + lane * 16 + i * 4];
        wz[i] = *(const float4*)&Whh[(size_t)(512  + j) * HD + lane * 16 + i * 4];
        wn[i] = *(const float4*)&Whh[(size_t)(1024 + j) * HD + lane * 16 + i * 4];
    }
    const float br = bhh[j], bz = bhh[512 + j], bn = bhh[1024 + j];
    float h_prev = 0.f;

    for (int t = 0; t < T_STEPS; t++) {
        // prefetch gate inputs (independent of h)
        const float* gp = &g_gi[(size_t)t * G3];
        float ir  = __ldg(gp + j);
        float iz  = __ldg(gp + 512 + j);
        float in_ = __ldg(gp + 1024 + j);

        float accr = 0.f, accz = 0.f, accn = 0.f;
        if (t > 0) {
            if (tid == 0) {
                unsigned v;
                do {
                    asm volatile("ld.acquire.gpu.global.u32 %0, [%1];"
                                 : "=r"(v) : "l"(&g_cnt[t - 1]) : "memory");
                } while (v < (unsigned)SCAN_CTAS);
            }
            __syncthreads();

            // stage h(t-1) into SMEM: one coalesced 4B .cg load per thread
            sh_hin[tid] = __ldcg(&g_hs[(size_t)(t - 1) * HD + tid]);
            __syncthreads();

            const float4* hp = (const float4*)&sh_hin[lane * 16];
#pragma unroll
            for (int i = 0; i < 4; i++) {
                float4 h4 = hp[i];
                accr += wr[i].x * h4.x + wr[i].y * h4.y + wr[i].z * h4.z + wr[i].w * h4.w;
                accz += wz[i].x * h4.x + wz[i].y * h4.y + wz[i].z * h4.z + wz[i].w * h4.w;
                accn += wn[i].x * h4.x + wn[i].y * h4.y + wn[i].z * h4.z + wn[i].w * h4.w;
            }
        }
#pragma unroll
        for (int off = 16; off > 0; off >>= 1) {
            accr += __shfl_xor_sync(0xffffffffu, accr, off);
            accz += __shfl_xor_sync(0xffffffffu, accz, off);
            accn += __shfl_xor_sync(0xffffffffu, accn, off);
        }
        float r = 1.f / (1.f + __expf(-(ir + accr + br)));
        float z = 1.f / (1.f + __expf(-(iz + accz + bz)));
        float n = tanhf(in_ + r * (accn + bn));
        float hn = (1.f - z) * n + z * h_prev;
        h_prev = hn;

        if (lane == 0) sh_h[warp] = hn;
        __syncthreads();
        if (tid < SCAN_WARPS) {
            // one coalesced 64B segment per CTA
            g_hs[(size_t)t * HD + blockIdx.x * SCAN_WARPS + tid] = sh_h[tid];
        }
        if (warp == 0) {
            __syncwarp();
            if (lane == 0) {
                asm volatile("red.release.gpu.global.add.u32 [%0], %1;"
                             :: "l"(&g_cnt[t]), "r"(1u) : "memory");
            }
        }
    }
}

// ---------------- K4a: logits[t] = dot(hs[t], w_att) -------------------------
__global__ __launch_bounds__(256) void k_logits(const float* __restrict__ watt) {
    const int warp = threadIdx.x >> 5, lane = threadIdx.x & 31;
    const int t = blockIdx.x * 8 + warp;
    float acc = 0.f;
#pragma unroll
    for (int i = 0; i < 4; i++) {
        float4 h4 = *(const float4*)&g_hs[(size_t)t * HD + lane * 16 + i * 4];
        float4 w4 = *(const float4*)&watt[lane * 16 + i * 4];
        acc += h4.x * w4.x + h4.y * w4.y + h4.z * w4.z + h4.w * w4.w;
    }
#pragma unroll
    for (int off = 16; off > 0; off >>= 1)
        acc += __shfl_xor_sync(0xffffffffu, acc, off);
    if (lane == 0) g_logits[t] = acc;
}

// ---------------- K4b: softmax over 4096 logits ------------------------------
__global__ __launch_bounds__(1024) void k_softmax() {
    __shared__ float red[1024];
    const int tid = threadIdx.x;
    float l[4];
    float m = -3.4e38f;
#pragma unroll
    for (int i = 0; i < 4; i++) {
        l[i] = g_logits[tid + i * 1024];
        m = fmaxf(m, l[i]);
    }
    red[tid] = m;
    __syncthreads();
    for (int s = 512; s > 0; s >>= 1) {
        if (tid < s) red[tid] = fmaxf(red[tid], red[tid + s]);
        __syncthreads();
    }
    const float M = red[0];
    __syncthreads();
    float e[4];
    float sum = 0.f;
#pragma unroll
    for (int i = 0; i < 4; i++) {
        e[i] = __expf(l[i] - M);
        sum += e[i];
    }
    red[tid] = sum;
    __syncthreads();
    for (int s = 512; s > 0; s >>= 1) {
        if (tid < s) red[tid] += red[tid + s];
        __syncthreads();
    }
    const float inv = 1.f / red[0];
#pragma unroll
    for (int i = 0; i < 4; i++) g_alpha[tid + i * 1024] = e[i] * inv;
}

// ---------------- K4c: out[j] = sum_t alpha[t] * hs[t][j] --------------------
__global__ __launch_bounds__(128) void k_out(float* __restrict__ out) {
    __shared__ float al[T_STEPS];
    const int j = blockIdx.x * 128 + threadIdx.x;
    for (int i = threadIdx.x; i < T_STEPS; i += 128) al[i] = g_alpha[i];
    __syncthreads();
    float acc = 0.f;
#pragma unroll 8
    for (int t = 0; t < T_STEPS; t++)
        acc += al[t] * g_hs[(size_t)t * HD + j];
    out[j] = acc;
}

// ---------------- launch ------------------------------------------------------
extern "C" void kernel_launch(void* const* d_in, const int* in_sizes, int n_in,
                              void* d_out, int out_size) {
    const float* H     = (const float*)d_in[0];
    // d_in[1] = TE (unused)
    const float* X     = (const float*)d_in[2];
    const float* W_ih  = (const float*)d_in[3];
    const float* W_hh  = (const float*)d_in[4];
    const float* b_ih  = (const float*)d_in[5];
    const float* b_hh  = (const float*)d_in[6];
    const float* w_att = (const float*)d_in[7];
    float* out = (float*)d_out;

    k_zero<<<4, 1024>>>();
    k_gemm1<<<dim3(32, 8), 256>>>(H, X);
    k_gemm2<<<dim3(32, 24), 256>>>(W_ih, b_ih);
    k_scan<<<SCAN_CTAS, 512>>>(W_hh, b_hh);
    k_logits<<<512, 256>>>(w_att);
    k_softmax<<<1, 1024>>>();
    k_out<<<4, 128>>>(out);
}

// round 7
// speedup vs baseline: 1.5742x; 1.1355x over previous
#include <cuda_runtime.h>
#include <cstdint>

#define T_STEPS 4096
#define HD      512
#define NC      4880
#define G3      1536
#define SCAN_CTAS 32
#define SCAN_WARPS 16   // warps per CTA; SCAN_CTAS*SCAN_WARPS == 512 units
#define SENT 0x7FC00BADu

// ---------------- scratch (device globals: no runtime allocation) ------------
__device__ float    g_visit[(size_t)T_STEPS * HD];    // 8 MB
__device__ float    g_gi[(size_t)T_STEPS * G3];       // 25 MB
__device__ float    g_hs[(size_t)T_STEPS * HD];       // 8 MB
__device__ float    g_logits[T_STEPS];
__device__ float    g_alpha[T_STEPS];

// ---------------- K0: poison g_hs with the NaN sentinel ----------------------
__global__ void k_poison() {
    size_t i = (size_t)blockIdx.x * 1024 + threadIdx.x;
    ((unsigned*)g_hs)[i] = SENT;
}

// ---------------- K1: visit_emb[t][j] = sum_c H[c][t] * X[c][j] --------------
__global__ __launch_bounds__(256) void k_gemm1(const float* __restrict__ H,
                                               const float* __restrict__ X) {
    __shared__ float As[16][128];
    __shared__ float Bs[16][64];
    const int t0 = blockIdx.x * 128, j0 = blockIdx.y * 64;
    const int tid = threadIdx.x;
    const int tx = tid & 15, ty = tid >> 4;

    float acc[8][4];
#pragma unroll
    for (int m = 0; m < 8; m++)
#pragma unroll
        for (int n = 0; n < 4; n++) acc[m][n] = 0.f;

    for (int c0 = 0; c0 < NC; c0 += 16) {
#pragma unroll
        for (int i = 0; i < 2; i++) {
            int idx = tid + i * 256;
            int r = idx >> 5, c4 = (idx & 31) << 2;
            *(float4*)&As[r][c4] =
                *(const float4*)&H[(size_t)(c0 + r) * T_STEPS + t0 + c4];
        }
        {
            int r = tid >> 4, c4 = (tid & 15) << 2;
            *(float4*)&Bs[r][c4] =
                *(const float4*)&X[(size_t)(c0 + r) * HD + j0 + c4];
        }
        __syncthreads();
#pragma unroll
        for (int kk = 0; kk < 16; kk++) {
            float4 a0 = *(float4*)&As[kk][ty * 8];
            float4 a1 = *(float4*)&As[kk][ty * 8 + 4];
            float4 b  = *(float4*)&Bs[kk][tx * 4];
            float a[8] = {a0.x, a0.y, a0.z, a0.w, a1.x, a1.y, a1.z, a1.w};
            float bb[4] = {b.x, b.y, b.z, b.w};
#pragma unroll
            for (int m = 0; m < 8; m++)
#pragma unroll
                for (int n = 0; n < 4; n++) acc[m][n] += a[m] * bb[n];
        }
        __syncthreads();
    }
#pragma unroll
    for (int m = 0; m < 8; m++) {
        float4 v = make_float4(acc[m][0], acc[m][1], acc[m][2], acc[m][3]);
        *(float4*)&g_visit[(size_t)(t0 + ty * 8 + m) * HD + j0 + tx * 4] = v;
    }
}

// ---------------- K2: gi[t][g] = sum_k visit[t][k] * W_ih[g][k] + b_ih[g] ----
__global__ __launch_bounds__(256) void k_gemm2(const float* __restrict__ W_ih,
                                               const float* __restrict__ b_ih) {
    __shared__ float As[32][129];   // As[k][t], padded
    __shared__ float Bs[32][64];    // Bs[k][g]
    const int t0 = blockIdx.x * 128, g0 = blockIdx.y * 64;
    const int tid = threadIdx.x;
    const int tx = tid & 15, ty = tid >> 4;

    float acc[8][4];
#pragma unroll
    for (int m = 0; m < 8; m++)
#pragma unroll
        for (int n = 0; n < 4; n++) acc[m][n] = 0.f;

    for (int k0 = 0; k0 < HD; k0 += 32) {
        {
            int t_l = tid >> 1;
#pragma unroll
            for (int i = 0; i < 4; i++) {
                int q = (tid & 1) + i * 2;   // 0..7
                float4 v = *(const float4*)&g_visit[(size_t)(t0 + t_l) * HD + k0 + q * 4];
                As[q * 4 + 0][t_l] = v.x; As[q * 4 + 1][t_l] = v.y;
                As[q * 4 + 2][t_l] = v.z; As[q * 4 + 3][t_l] = v.w;
            }
        }
        {
            int g_l = tid >> 2;
#pragma unroll
            for (int i = 0; i < 2; i++) {
                int q = (tid & 3) + i * 4;   // 0..7
                float4 w = *(const float4*)&W_ih[(size_t)(g0 + g_l) * HD + k0 + q * 4];
                Bs[q * 4 + 0][g_l] = w.x; Bs[q * 4 + 1][g_l] = w.y;
                Bs[q * 4 + 2][g_l] = w.z; Bs[q * 4 + 3][g_l] = w.w;
            }
        }
        __syncthreads();
#pragma unroll
        for (int kk = 0; kk < 32; kk++) {
            float a[8];
#pragma unroll
            for (int m = 0; m < 8; m++) a[m] = As[kk][ty * 8 + m];
            float4 b = *(float4*)&Bs[kk][tx * 4];
            float bb[4] = {b.x, b.y, b.z, b.w};
#pragma unroll
            for (int m = 0; m < 8; m++)
#pragma unroll
                for (int n = 0; n < 4; n++) acc[m][n] += a[m] * bb[n];
        }
        __syncthreads();
    }
    float4 bias = *(const float4*)&b_ih[g0 + tx * 4];
    float bb[4] = {bias.x, bias.y, bias.z, bias.w};
#pragma unroll
    for (int m = 0; m < 8; m++) {
        float4 v = make_float4(acc[m][0] + bb[0], acc[m][1] + bb[1],
                               acc[m][2] + bb[2], acc[m][3] + bb[3]);
        *(float4*)&g_gi[(size_t)(t0 + ty * 8 + m) * G3 + g0 + tx * 4] = v;
    }
}

// ---------------- K3: persistent GRU scan (data-is-the-flag, relaxed atomics)
// 32 CTAs x 512 threads; warp w of CTA b owns unit j = b*16 + w; W_hh rows in
// registers. g_hs is pre-poisoned with SENT (a NaN pattern the GRU can never
// produce). Per step:
//   * each thread polls ITS OWN word of h(t-1) with ld.relaxed.gpu until
//     != SENT (morally-strong: coherent, no tearing; detect+load fused in one
//     L2 round trip), stages into parity-double-buffered SMEM, ONE bar
//   * dot products from SMEM, butterfly reduce, gate math
//   * lane0 publishes h(t)[j] with ONE st.relaxed.gpu -- the value IS the flag
// No counters, no fences, no membars; one __syncthreads per step.
__global__ __launch_bounds__(512) void k_scan(const float* __restrict__ Whh,
                                              const float* __restrict__ bhh) {
    __shared__ float sh_hin[2][HD];
    const int tid = threadIdx.x;
    const int warp = tid >> 5, lane = tid & 31;
    const int j = blockIdx.x * SCAN_WARPS + warp;

    float4 wr[4], wz[4], wn[4];
#pragma unroll
    for (int i = 0; i < 4; i++) {
        wr[i] = *(const float4*)&Whh[(size_t)j * HD          + lane * 16 + i * 4];
        wz[i] = *(const float4*)&Whh[(size_t)(512  + j) * HD + lane * 16 + i * 4];
        wn[i] = *(const float4*)&Whh[(size_t)(1024 + j) * HD + lane * 16 + i * 4];
    }
    const float br = bhh[j], bz = bhh[512 + j], bn = bhh[1024 + j];
    float h_prev = 0.f;

    for (int t = 0; t < T_STEPS; t++) {
        // prefetch gate inputs (independent of h)
        const float* gp = &g_gi[(size_t)t * G3];
        float ir  = __ldg(gp + j);
        float iz  = __ldg(gp + 512 + j);
        float in_ = __ldg(gp + 1024 + j);

        float accr = 0.f, accz = 0.f, accn = 0.f;
        if (t > 0) {
            // poll own word of h(t-1): morally-strong relaxed load
            const float* src = &g_hs[(size_t)(t - 1) * HD + tid];
            unsigned u;
            do {
                asm volatile("ld.relaxed.gpu.global.b32 %0, [%1];"
                             : "=r"(u) : "l"(src) : "memory");
            } while (u == SENT);
            sh_hin[t & 1][tid] = __uint_as_float(u);
            __syncthreads();

            const float4* hp = (const float4*)&sh_hin[t & 1][lane * 16];
#pragma unroll
            for (int i = 0; i < 4; i++) {
                float4 h4 = hp[i];
                accr += wr[i].x * h4.x + wr[i].y * h4.y + wr[i].z * h4.z + wr[i].w * h4.w;
                accz += wz[i].x * h4.x + wz[i].y * h4.y + wz[i].z * h4.z + wz[i].w * h4.w;
                accn += wn[i].x * h4.x + wn[i].y * h4.y + wn[i].z * h4.z + wn[i].w * h4.w;
            }
        }
#pragma unroll
        for (int off = 16; off > 0; off >>= 1) {
            accr += __shfl_xor_sync(0xffffffffu, accr, off);
            accz += __shfl_xor_sync(0xffffffffu, accz, off);
            accn += __shfl_xor_sync(0xffffffffu, accn, off);
        }
        float r = 1.f / (1.f + __expf(-(ir + accr + br)));
        float z = 1.f / (1.f + __expf(-(iz + accz + bz)));
        float n = tanhf(in_ + r * (accn + bn));
        float hn = (1.f - z) * n + z * h_prev;
        h_prev = hn;

        if (lane == 0) {
            asm volatile("st.relaxed.gpu.global.b32 [%0], %1;"
                         :: "l"(&g_hs[(size_t)t * HD + j]),
                            "r"(__float_as_uint(hn)) : "memory");
        }
    }
}

// ---------------- K4a: logits[t] = dot(hs[t], w_att) -------------------------
__global__ __launch_bounds__(256) void k_logits(const float* __restrict__ watt) {
    const int warp = threadIdx.x >> 5, lane = threadIdx.x & 31;
    const int t = blockIdx.x * 8 + warp;
    float acc = 0.f;
#pragma unroll
    for (int i = 0; i < 4; i++) {
        float4 h4 = *(const float4*)&g_hs[(size_t)t * HD + lane * 16 + i * 4];
        float4 w4 = *(const float4*)&watt[lane * 16 + i * 4];
        acc += h4.x * w4.x + h4.y * w4.y + h4.z * w4.z + h4.w * w4.w;
    }
#pragma unroll
    for (int off = 16; off > 0; off >>= 1)
        acc += __shfl_xor_sync(0xffffffffu, acc, off);
    if (lane == 0) g_logits[t] = acc;
}

// ---------------- K4b: softmax over 4096 logits ------------------------------
__global__ __launch_bounds__(1024) void k_softmax() {
    __shared__ float red[1024];
    const int tid = threadIdx.x;
    float l[4];
    float m = -3.4e38f;
#pragma unroll
    for (int i = 0; i < 4; i++) {
        l[i] = g_logits[tid + i * 1024];
        m = fmaxf(m, l[i]);
    }
    red[tid] = m;
    __syncthreads();
    for (int s = 512; s > 0; s >>= 1) {
        if (tid < s) red[tid] = fmaxf(red[tid], red[tid + s]);
        __syncthreads();
    }
    const float M = red[0];
    __syncthreads();
    float e[4];
    float sum = 0.f;
#pragma unroll
    for (int i = 0; i < 4; i++) {
        e[i] = __expf(l[i] - M);
        sum += e[i];
    }
    red[tid] = sum;
    __syncthreads();
    for (int s = 512; s > 0; s >>= 1) {
        if (tid < s) red[tid] += red[tid + s];
        __syncthreads();
    }
    const float inv = 1.f / red[0];
#pragma unroll
    for (int i = 0; i < 4; i++) g_alpha[tid + i * 1024] = e[i] * inv;
}

// ---------------- K4c: out[j] = sum_t alpha[t] * hs[t][j] --------------------
__global__ __launch_bounds__(128) void k_out(float* __restrict__ out) {
    __shared__ float al[T_STEPS];
    const int j = blockIdx.x * 128 + threadIdx.x;
    for (int i = threadIdx.x; i < T_STEPS; i += 128) al[i] = g_alpha[i];
    __syncthreads();
    float acc = 0.f;
#pragma unroll 8
    for (int t = 0; t < T_STEPS; t++)
        acc += al[t] * g_hs[(size_t)t * HD + j];
    out[j] = acc;
}

// ---------------- launch ------------------------------------------------------
extern "C" void kernel_launch(void* const* d_in, const int* in_sizes, int n_in,
                              void* d_out, int out_size) {
    const float* H     = (const float*)d_in[0];
    // d_in[1] = TE (unused)
    const float* X     = (const float*)d_in[2];
    const float* W_ih  = (const float*)d_in[3];
    const float* W_hh  = (const float*)d_in[4];
    const float* b_ih  = (const float*)d_in[5];
    const float* b_hh  = (const float*)d_in[6];
    const float* w_att = (const float*)d_in[7];
    float* out = (float*)d_out;

    k_poison<<<(T_STEPS * HD) / 1024, 1024>>>();
    k_gemm1<<<dim3(32, 8), 256>>>(H, X);
    k_gemm2<<<dim3(32, 24), 256>>>(W_ih, b_ih);
    k_scan<<<SCAN_CTAS, 512>>>(W_hh, b_hh);
    k_logits<<<512, 256>>>(w_att);
    k_softmax<<<1, 1024>>>();
    k_out<<<4, 128>>>(out);
}

// round 11
// speedup vs baseline: 1.6219x; 1.0303x over previous
#include <cuda_runtime.h>
#include <cstdint>

#define T_STEPS 4096
#define HD      512
#define NC      4880
#define G3      1536
#define SCAN_CTAS 32
#define SCAN_WARPS 16   // warps per CTA; SCAN_CTAS*SCAN_WARPS == 512 units
#define SENT 0x7FC00BADu

// packed dual-fp32 FMA (PTX-only instruction; bit-exact 2x fp32 FMA)
#define FMA2(d, a, b, c) \
    asm("fma.rn.f32x2 %0, %1, %2, %3;" : "=l"(d) : "l"(a), "l"(b), "l"(c))

__device__ __forceinline__ float u64lo(unsigned long long v) {
    return __uint_as_float((unsigned)v);
}
__device__ __forceinline__ float u64hi(unsigned long long v) {
    return __uint_as_float((unsigned)(v >> 32));
}

// ---------------- scratch (device globals: no runtime allocation) ------------
__device__ float    g_visit[(size_t)T_STEPS * HD];    // 8 MB
__device__ float    g_gi[(size_t)T_STEPS * G3];       // 25 MB
__device__ float    g_hs[(size_t)T_STEPS * HD];       // 8 MB
__device__ float    g_logits[T_STEPS];
__device__ float    g_alpha[T_STEPS];

// ---------------- K0: poison g_hs with the NaN sentinel ----------------------
__global__ void k_poison() {
    size_t i = (size_t)blockIdx.x * 1024 + threadIdx.x;
    ((unsigned*)g_hs)[i] = SENT;
}

// ---------------- K1: visit_emb[t][j] = sum_c H[c][t] * X[c][j] --------------
__global__ __launch_bounds__(256) void k_gemm1(const float* __restrict__ H,
                                               const float* __restrict__ X) {
    __shared__ float As[16][128];
    __shared__ float Bs[16][64];
    const int t0 = blockIdx.x * 128, j0 = blockIdx.y * 64;
    const int tid = threadIdx.x;
    const int tx = tid & 15, ty = tid >> 4;

    float acc[8][4];
#pragma unroll
    for (int m = 0; m < 8; m++)
#pragma unroll
        for (int n = 0; n < 4; n++) acc[m][n] = 0.f;

    for (int c0 = 0; c0 < NC; c0 += 16) {
#pragma unroll
        for (int i = 0; i < 2; i++) {
            int idx = tid + i * 256;
            int r = idx >> 5, c4 = (idx & 31) << 2;
            *(float4*)&As[r][c4] =
                *(const float4*)&H[(size_t)(c0 + r) * T_STEPS + t0 + c4];
        }
        {
            int r = tid >> 4, c4 = (tid & 15) << 2;
            *(float4*)&Bs[r][c4] =
                *(const float4*)&X[(size_t)(c0 + r) * HD + j0 + c4];
        }
        __syncthreads();
#pragma unroll
        for (int kk = 0; kk < 16; kk++) {
            float4 a0 = *(float4*)&As[kk][ty * 8];
            float4 a1 = *(float4*)&As[kk][ty * 8 + 4];
            float4 b  = *(float4*)&Bs[kk][tx * 4];
            float a[8] = {a0.x, a0.y, a0.z, a0.w, a1.x, a1.y, a1.z, a1.w};
            float bb[4] = {b.x, b.y, b.z, b.w};
#pragma unroll
            for (int m = 0; m < 8; m++)
#pragma unroll
                for (int n = 0; n < 4; n++) acc[m][n] += a[m] * bb[n];
        }
        __syncthreads();
    }
#pragma unroll
    for (int m = 0; m < 8; m++) {
        float4 v = make_float4(acc[m][0], acc[m][1], acc[m][2], acc[m][3]);
        *(float4*)&g_visit[(size_t)(t0 + ty * 8 + m) * HD + j0 + tx * 4] = v;
    }
}

// ---------------- K2: gi[t][g] = sum_k visit[t][k] * W_ih[g][k] + b_ih[g] ----
__global__ __launch_bounds__(256) void k_gemm2(const float* __restrict__ W_ih,
                                               const float* __restrict__ b_ih) {
    __shared__ float As[32][129];   // As[k][t], padded
    __shared__ float Bs[32][64];    // Bs[k][g]
    const int t0 = blockIdx.x * 128, g0 = blockIdx.y * 64;
    const int tid = threadIdx.x;
    const int tx = tid & 15, ty = tid >> 4;

    float acc[8][4];
#pragma unroll
    for (int m = 0; m < 8; m++)
#pragma unroll
        for (int n = 0; n < 4; n++) acc[m][n] = 0.f;

    for (int k0 = 0; k0 < HD; k0 += 32) {
        {
            int t_l = tid >> 1;
#pragma unroll
            for (int i = 0; i < 4; i++) {
                int q = (tid & 1) + i * 2;   // 0..7
                float4 v = *(const float4*)&g_visit[(size_t)(t0 + t_l) * HD + k0 + q * 4];
                As[q * 4 + 0][t_l] = v.x; As[q * 4 + 1][t_l] = v.y;
                As[q * 4 + 2][t_l] = v.z; As[q * 4 + 3][t_l] = v.w;
            }
        }
        {
            int g_l = tid >> 2;
#pragma unroll
            for (int i = 0; i < 2; i++) {
                int q = (tid & 3) + i * 4;   // 0..7
                float4 w = *(const float4*)&W_ih[(size_t)(g0 + g_l) * HD + k0 + q * 4];
                Bs[q * 4 + 0][g_l] = w.x; Bs[q * 4 + 1][g_l] = w.y;
                Bs[q * 4 + 2][g_l] = w.z; Bs[q * 4 + 3][g_l] = w.w;
            }
        }
        __syncthreads();
#pragma unroll
        for (int kk = 0; kk < 32; kk++) {
            float a[8];
#pragma unroll
            for (int m = 0; m < 8; m++) a[m] = As[kk][ty * 8 + m];
            float4 b = *(float4*)&Bs[kk][tx * 4];
            float bb[4] = {b.x, b.y, b.z, b.w};
#pragma unroll
            for (int m = 0; m < 8; m++)
#pragma unroll
                for (int n = 0; n < 4; n++) acc[m][n] += a[m] * bb[n];
        }
        __syncthreads();
    }
    float4 bias = *(const float4*)&b_ih[g0 + tx * 4];
    float bb[4] = {bias.x, bias.y, bias.z, bias.w};
#pragma unroll
    for (int m = 0; m < 8; m++) {
        float4 v = make_float4(acc[m][0] + bb[0], acc[m][1] + bb[1],
                               acc[m][2] + bb[2], acc[m][3] + bb[3]);
        *(float4*)&g_gi[(size_t)(t0 + ty * 8 + m) * G3 + g0 + tx * 4] = v;
    }
}

// ---------------- K3: persistent GRU scan (data-is-the-flag, relaxed atomics)
// 32 CTAs x 512 threads; warp w of CTA b owns unit j = b*16 + w; W_hh rows in
// registers as f32x2 pairs. g_hs pre-poisoned with SENT.
// Lane l owns h components {i*128 + 4l .. 4l+3 : i=0..3}: lane SMEM addresses
// stride 16B -> conflict-free LDS.128 (was 4-way conflicted at stride 64B).
// Dot products use fma.rn.f32x2 (24 FFMA2/thread instead of 48 FFMA).
// Per step: poll own word of h(t-1) (ld.relaxed.gpu; detect+load fused),
// stage to parity-double-buffered SMEM, ONE bar, dots, butterfly reduce,
// gates, lane0 publishes with ONE st.relaxed.gpu. No counters, no fences.
__global__ __launch_bounds__(512) void k_scan(const float* __restrict__ Whh,
                                              const float* __restrict__ bhh) {
    __shared__ float sh_hin[2][HD];
    const int tid = threadIdx.x;
    const int warp = tid >> 5, lane = tid & 31;
    const int j = blockIdx.x * SCAN_WARPS + warp;

    // weights packed as f32x2 pairs; lane l, chunk i covers comps i*128+4l..+3
    ulonglong2 wr[4], wz[4], wn[4];
#pragma unroll
    for (int i = 0; i < 4; i++) {
        wr[i] = *(const ulonglong2*)&Whh[(size_t)j * HD          + i * 128 + lane * 4];
        wz[i] = *(const ulonglong2*)&Whh[(size_t)(512  + j) * HD + i * 128 + lane * 4];
        wn[i] = *(const ulonglong2*)&Whh[(size_t)(1024 + j) * HD + i * 128 + lane * 4];
    }
    const float br = bhh[j], bz = bhh[512 + j], bn = bhh[1024 + j];
    float h_prev = 0.f;

    for (int t = 0; t < T_STEPS; t++) {
        // prefetch gate inputs (independent of h)
        const float* gp = &g_gi[(size_t)t * G3];
        float ir  = __ldg(gp + j);
        float iz  = __ldg(gp + 512 + j);
        float in_ = __ldg(gp + 1024 + j);

        float accr = 0.f, accz = 0.f, accn = 0.f;
        if (t > 0) {
            // poll own word of h(t-1): morally-strong relaxed load
            const float* src = &g_hs[(size_t)(t - 1) * HD + tid];
            unsigned u;
            do {
                asm volatile("ld.relaxed.gpu.global.b32 %0, [%1];"
                             : "=r"(u) : "l"(src) : "memory");
            } while (u == SENT);
            sh_hin[t & 1][tid] = __uint_as_float(u);
            __syncthreads();

            unsigned long long ar0 = 0, ar1 = 0, az0 = 0, az1 = 0, an0 = 0, an1 = 0;
#pragma unroll
            for (int i = 0; i < 4; i++) {
                ulonglong2 h2 = *(const ulonglong2*)&sh_hin[t & 1][i * 128 + lane * 4];
                FMA2(ar0, wr[i].x, h2.x, ar0);
                FMA2(ar1, wr[i].y, h2.y, ar1);
                FMA2(az0, wz[i].x, h2.x, az0);
                FMA2(az1, wz[i].y, h2.y, az1);
                FMA2(an0, wn[i].x, h2.x, an0);
                FMA2(an1, wn[i].y, h2.y, an1);
            }
            accr = (u64lo(ar0) + u64hi(ar0)) + (u64lo(ar1) + u64hi(ar1));
            accz = (u64lo(az0) + u64hi(az0)) + (u64lo(az1) + u64hi(az1));
            accn = (u64lo(an0) + u64hi(an0)) + (u64lo(an1) + u64hi(an1));
        }
#pragma unroll
        for (int off = 16; off > 0; off >>= 1) {
            accr += __shfl_xor_sync(0xffffffffu, accr, off);
            accz += __shfl_xor_sync(0xffffffffu, accz, off);
            accn += __shfl_xor_sync(0xffffffffu, accn, off);
        }
        float r = 1.f / (1.f + __expf(-(ir + accr + br)));
        float z = 1.f / (1.f + __expf(-(iz + accz + bz)));
        float n = tanhf(in_ + r * (accn + bn));
        float hn = (1.f - z) * n + z * h_prev;
        h_prev = hn;

        if (lane == 0) {
            asm volatile("st.relaxed.gpu.global.b32 [%0], %1;"
                         :: "l"(&g_hs[(size_t)t * HD + j]),
                            "r"(__float_as_uint(hn)) : "memory");
        }
    }
}

// ---------------- K4a: logits[t] = dot(hs[t], w_att) -------------------------
__global__ __launch_bounds__(256) void k_logits(const float* __restrict__ watt) {
    const int warp = threadIdx.x >> 5, lane = threadIdx.x & 31;
    const int t = blockIdx.x * 8 + warp;
    float acc = 0.f;
#pragma unroll
    for (int i = 0; i < 4; i++) {
        float4 h4 = *(const float4*)&g_hs[(size_t)t * HD + lane * 16 + i * 4];
        float4 w4 = *(const float4*)&watt[lane * 16 + i * 4];
        acc += h4.x * w4.x + h4.y * w4.y + h4.z * w4.z + h4.w * w4.w;
    }
#pragma unroll
    for (int off = 16; off > 0; off >>= 1)
        acc += __shfl_xor_sync(0xffffffffu, acc, off);
    if (lane == 0) g_logits[t] = acc;
}

// ---------------- K4b: softmax over 4096 logits ------------------------------
__global__ __launch_bounds__(1024) void k_softmax() {
    __shared__ float red[1024];
    const int tid = threadIdx.x;
    float l[4];
    float m = -3.4e38f;
#pragma unroll
    for (int i = 0; i < 4; i++) {
        l[i] = g_logits[tid + i * 1024];
        m = fmaxf(m, l[i]);
    }
    red[tid] = m;
    __syncthreads();
    for (int s = 512; s > 0; s >>= 1) {
        if (tid < s) red[tid] = fmaxf(red[tid], red[tid + s]);
        __syncthreads();
    }
    const float M = red[0];
    __syncthreads();
    float e[4];
    float sum = 0.f;
#pragma unroll
    for (int i = 0; i < 4; i++) {
        e[i] = __expf(l[i] - M);
        sum += e[i];
    }
    red[tid] = sum;
    __syncthreads();
    for (int s = 512; s > 0; s >>= 1) {
        if (tid < s) red[tid] += red[tid + s];
        __syncthreads();
    }
    const float inv = 1.f / red[0];
#pragma unroll
    for (int i = 0; i < 4; i++) g_alpha[tid + i * 1024] = e[i] * inv;
}

// ---------------- K4c: out[j] = sum_t alpha[t] * hs[t][j] --------------------
__global__ __launch_bounds__(128) void k_out(float* __restrict__ out) {
    __shared__ float al[T_STEPS];
    const int j = blockIdx.x * 128 + threadIdx.x;
    for (int i = threadIdx.x; i < T_STEPS; i += 128) al[i] = g_alpha[i];
    __syncthreads();
    float acc = 0.f;
#pragma unroll 8
    for (int t = 0; t < T_STEPS; t++)
        acc += al[t] * g_hs[(size_t)t * HD + j];
    out[j] = acc;
}

// ---------------- launch ------------------------------------------------------
extern "C" void kernel_launch(void* const* d_in, const int* in_sizes, int n_in,
                              void* d_out, int out_size) {
    const float* H     = (const float*)d_in[0];
    // d_in[1] = TE (unused)
    const float* X     = (const float*)d_in[2];
    const float* W_ih  = (const float*)d_in[3];
    const float* W_hh  = (const float*)d_in[4];
    const float* b_ih  = (const float*)d_in[5];
    const float* b_hh  = (const float*)d_in[6];
    const float* w_att = (const float*)d_in[7];
    float* out = (float*)d_out;

    k_poison<<<(T_STEPS * HD) / 1024, 1024>>>();
    k_gemm1<<<dim3(32, 8), 256>>>(H, X);
    k_gemm2<<<dim3(32, 24), 256>>>(W_ih, b_ih);
    k_scan<<<SCAN_CTAS, 512>>>(W_hh, b_hh);
    k_logits<<<512, 256>>>(w_att);
    k_softmax<<<1, 1024>>>();
    k_out<<<4, 128>>>(out);
}

// round 15
// speedup vs baseline: 1.8207x; 1.1226x over previous
#include <cuda_runtime.h>
#include <cstdint>

#define T_STEPS 4096
#define HD      512
#define NC      4880
#define G3      1536
#define SCAN_CTAS 32
#define SCAN_WARPS 16   // warps per CTA; SCAN_CTAS*SCAN_WARPS == 512 units
#define SENT 0x7FC00BADu

// packed dual-fp32 FMA (PTX-only instruction; bit-exact 2x fp32 FMA)
#define FMA2(d, a, b, c) \
    asm("fma.rn.f32x2 %0, %1, %2, %3;" : "=l"(d) : "l"(a), "l"(b), "l"(c))

__device__ __forceinline__ float u64lo(unsigned long long v) {
    return __uint_as_float((unsigned)v);
}
__device__ __forceinline__ float u64hi(unsigned long long v) {
    return __uint_as_float((unsigned)(v >> 32));
}

// ---------------- scratch (device globals: no runtime allocation) ------------
__device__ float    g_visit[(size_t)T_STEPS * HD];    // 8 MB
__device__ float    g_gi[(size_t)T_STEPS * G3];       // 25 MB
__device__ float    g_hs[(size_t)T_STEPS * HD];       // 8 MB
__device__ float    g_logits[T_STEPS];
__device__ float    g_alpha[T_STEPS];

// ---------------- K0: poison g_hs with the NaN sentinel ----------------------
__global__ void k_poison() {
    size_t i = (size_t)blockIdx.x * 1024 + threadIdx.x;
    ((unsigned*)g_hs)[i] = SENT;
}

// ---------------- K1: visit_emb[t][j] = sum_c H[c][t] * X[c][j] --------------
__global__ __launch_bounds__(256) void k_gemm1(const float* __restrict__ H,
                                               const float* __restrict__ X) {
    __shared__ float As[16][128];
    __shared__ float Bs[16][64];
    const int t0 = blockIdx.x * 128, j0 = blockIdx.y * 64;
    const int tid = threadIdx.x;
    const int tx = tid & 15, ty = tid >> 4;

    float acc[8][4];
#pragma unroll
    for (int m = 0; m < 8; m++)
#pragma unroll
        for (int n = 0; n < 4; n++) acc[m][n] = 0.f;

    for (int c0 = 0; c0 < NC; c0 += 16) {
#pragma unroll
        for (int i = 0; i < 2; i++) {
            int idx = tid + i * 256;
            int r = idx >> 5, c4 = (idx & 31) << 2;
            *(float4*)&As[r][c4] =
                *(const float4*)&H[(size_t)(c0 + r) * T_STEPS + t0 + c4];
        }
        {
            int r = tid >> 4, c4 = (tid & 15) << 2;
            *(float4*)&Bs[r][c4] =
                *(const float4*)&X[(size_t)(c0 + r) * HD + j0 + c4];
        }
        __syncthreads();
#pragma unroll
        for (int kk = 0; kk < 16; kk++) {
            float4 a0 = *(float4*)&As[kk][ty * 8];
            float4 a1 = *(float4*)&As[kk][ty * 8 + 4];
            float4 b  = *(float4*)&Bs[kk][tx * 4];
            float a[8] = {a0.x, a0.y, a0.z, a0.w, a1.x, a1.y, a1.z, a1.w};
            float bb[4] = {b.x, b.y, b.z, b.w};
#pragma unroll
            for (int m = 0; m < 8; m++)
#pragma unroll
                for (int n = 0; n < 4; n++) acc[m][n] += a[m] * bb[n];
        }
        __syncthreads();
    }
#pragma unroll
    for (int m = 0; m < 8; m++) {
        float4 v = make_float4(acc[m][0], acc[m][1], acc[m][2], acc[m][3]);
        *(float4*)&g_visit[(size_t)(t0 + ty * 8 + m) * HD + j0 + tx * 4] = v;
    }
}

// ---------------- K2: gi[t][g] = sum_k visit[t][k] * W_ih[g][k] + b_ih[g] ----
__global__ __launch_bounds__(256) void k_gemm2(const float* __restrict__ W_ih,
                                               const float* __restrict__ b_ih) {
    __shared__ float As[32][129];   // As[k][t], padded
    __shared__ float Bs[32][64];    // Bs[k][g]
    const int t0 = blockIdx.x * 128, g0 = blockIdx.y * 64;
    const int tid = threadIdx.x;
    const int tx = tid & 15, ty = tid >> 4;

    float acc[8][4];
#pragma unroll
    for (int m = 0; m < 8; m++)
#pragma unroll
        for (int n = 0; n < 4; n++) acc[m][n] = 0.f;

    for (int k0 = 0; k0 < HD; k0 += 32) {
        {
            int t_l = tid >> 1;
#pragma unroll
            for (int i = 0; i < 4; i++) {
                int q = (tid & 1) + i * 2;   // 0..7
                float4 v = *(const float4*)&g_visit[(size_t)(t0 + t_l) * HD + k0 + q * 4];
                As[q * 4 + 0][t_l] = v.x; As[q * 4 + 1][t_l] = v.y;
                As[q * 4 + 2][t_l] = v.z; As[q * 4 + 3][t_l] = v.w;
            }
        }
        {
            int g_l = tid >> 2;
#pragma unroll
            for (int i = 0; i < 2; i++) {
                int q = (tid & 3) + i * 4;   // 0..7
                float4 w = *(const float4*)&W_ih[(size_t)(g0 + g_l) * HD + k0 + q * 4];
                Bs[q * 4 + 0][g_l] = w.x; Bs[q * 4 + 1][g_l] = w.y;
                Bs[q * 4 + 2][g_l] = w.z; Bs[q * 4 + 3][g_l] = w.w;
            }
        }
        __syncthreads();
#pragma unroll
        for (int kk = 0; kk < 32; kk++) {
            float a[8];
#pragma unroll
            for (int m = 0; m < 8; m++) a[m] = As[kk][ty * 8 + m];
            float4 b = *(float4*)&Bs[kk][tx * 4];
            float bb[4] = {b.x, b.y, b.z, b.w};
#pragma unroll
            for (int m = 0; m < 8; m++)
#pragma unroll
                for (int n = 0; n < 4; n++) acc[m][n] += a[m] * bb[n];
        }
        __syncthreads();
    }
    float4 bias = *(const float4*)&b_ih[g0 + tx * 4];
    float bb[4] = {bias.x, bias.y, bias.z, bias.w};
#pragma unroll
    for (int m = 0; m < 8; m++) {
        float4 v = make_float4(acc[m][0] + bb[0], acc[m][1] + bb[1],
                               acc[m][2] + bb[2], acc[m][3] + bb[3]);
        *(float4*)&g_gi[(size_t)(t0 + ty * 8 + m) * G3 + g0 + tx * 4] = v;
    }
}

// ---------------- K3: persistent GRU scan (data-is-the-flag, relaxed atomics)
// 32 CTAs x 512 threads; warp w of CTA b owns unit j = b*16 + w; W_hh rows in
// registers as f32x2 pairs. g_hs pre-poisoned with SENT.
// Poll loop now backs off with __nanosleep(64) after a miss: 16K spinning
// threads were saturating the 16 LTS slices holding the h lines (ncu showed
// ~4.3TB/s of L2 read traffic vs ~37GB/s of real data), inflating the poll
// round trip. Backoff collapses the storm; detection quantum +~60ns mean.
// Gate n uses tanh(x) = 2*sigmoid(2x)-1 via EX2+RCP (shorter MUFU chain).
__global__ __launch_bounds__(512) void k_scan(const float* __restrict__ Whh,
                                              const float* __restrict__ bhh) {
    __shared__ float sh_hin[2][HD];
    const int tid = threadIdx.x;
    const int warp = tid >> 5, lane = tid & 31;
    const int j = blockIdx.x * SCAN_WARPS + warp;

    // weights packed as f32x2 pairs; lane l, chunk i covers comps i*128+4l..+3
    ulonglong2 wr[4], wz[4], wn[4];
#pragma unroll
    for (int i = 0; i < 4; i++) {
        wr[i] = *(const ulonglong2*)&Whh[(size_t)j * HD          + i * 128 + lane * 4];
        wz[i] = *(const ulonglong2*)&Whh[(size_t)(512  + j) * HD + i * 128 + lane * 4];
        wn[i] = *(const ulonglong2*)&Whh[(size_t)(1024 + j) * HD + i * 128 + lane * 4];
    }
    const float br = bhh[j], bz = bhh[512 + j], bn = bhh[1024 + j];
    float h_prev = 0.f;

    for (int t = 0; t < T_STEPS; t++) {
        // prefetch gate inputs (independent of h)
        const float* gp = &g_gi[(size_t)t * G3];
        float ir  = __ldg(gp + j);
        float iz  = __ldg(gp + 512 + j);
        float in_ = __ldg(gp + 1024 + j);

        float accr = 0.f, accz = 0.f, accn = 0.f;
        if (t > 0) {
            // poll own word of h(t-1): relaxed load; nanosleep backoff on miss
            const float* src = &g_hs[(size_t)(t - 1) * HD + tid];
            unsigned u;
            asm volatile("ld.relaxed.gpu.global.b32 %0, [%1];"
                         : "=r"(u) : "l"(src) : "memory");
            while (u == SENT) {
                __nanosleep(64);
                asm volatile("ld.relaxed.gpu.global.b32 %0, [%1];"
                             : "=r"(u) : "l"(src) : "memory");
            }
            sh_hin[t & 1][tid] = __uint_as_float(u);
            __syncthreads();

            unsigned long long ar0 = 0, ar1 = 0, az0 = 0, az1 = 0, an0 = 0, an1 = 0;
#pragma unroll
            for (int i = 0; i < 4; i++) {
                ulonglong2 h2 = *(const ulonglong2*)&sh_hin[t & 1][i * 128 + lane * 4];
                FMA2(ar0, wr[i].x, h2.x, ar0);
                FMA2(ar1, wr[i].y, h2.y, ar1);
                FMA2(az0, wz[i].x, h2.x, az0);
                FMA2(az1, wz[i].y, h2.y, az1);
                FMA2(an0, wn[i].x, h2.x, an0);
                FMA2(an1, wn[i].y, h2.y, an1);
            }
            accr = (u64lo(ar0) + u64hi(ar0)) + (u64lo(ar1) + u64hi(ar1));
            accz = (u64lo(az0) + u64hi(az0)) + (u64lo(az1) + u64hi(az1));
            accn = (u64lo(an0) + u64hi(an0)) + (u64lo(an1) + u64hi(an1));
        }
#pragma unroll
        for (int off = 16; off > 0; off >>= 1) {
            accr += __shfl_xor_sync(0xffffffffu, accr, off);
            accz += __shfl_xor_sync(0xffffffffu, accz, off);
            accn += __shfl_xor_sync(0xffffffffu, accn, off);
        }
        float r = 1.f / (1.f + __expf(-(ir + accr + br)));
        float z = 1.f / (1.f + __expf(-(iz + accz + bz)));
        // tanh(x) = 2*sigmoid(2x) - 1 (EX2+RCP chain, shorter than tanhf)
        float nx = in_ + r * (accn + bn);
        float n = __fmaf_rn(2.f, 1.f / (1.f + __expf(-2.f * nx)), -1.f);
        float hn = (1.f - z) * n + z * h_prev;
        h_prev = hn;

        if (lane == 0) {
            asm volatile("st.relaxed.gpu.global.b32 [%0], %1;"
                         :: "l"(&g_hs[(size_t)t * HD + j]),
                            "r"(__float_as_uint(hn)) : "memory");
        }
    }
}

// ---------------- K4a: logits[t] = dot(hs[t], w_att) -------------------------
__global__ __launch_bounds__(256) void k_logits(const float* __restrict__ watt) {
    const int warp = threadIdx.x >> 5, lane = threadIdx.x & 31;
    const int t = blockIdx.x * 8 + warp;
    float acc = 0.f;
#pragma unroll
    for (int i = 0; i < 4; i++) {
        float4 h4 = *(const float4*)&g_hs[(size_t)t * HD + lane * 16 + i * 4];
        float4 w4 = *(const float4*)&watt[lane * 16 + i * 4];
        acc += h4.x * w4.x + h4.y * w4.y + h4.z * w4.z + h4.w * w4.w;
    }
#pragma unroll
    for (int off = 16; off > 0; off >>= 1)
        acc += __shfl_xor_sync(0xffffffffu, acc, off);
    if (lane == 0) g_logits[t] = acc;
}

// ---------------- K4b: softmax over 4096 logits ------------------------------
__global__ __launch_bounds__(1024) void k_softmax() {
    __shared__ float red[1024];
    const int tid = threadIdx.x;
    float l[4];
    float m = -3.4e38f;
#pragma unroll
    for (int i = 0; i < 4; i++) {
        l[i] = g_logits[tid + i * 1024];
        m = fmaxf(m, l[i]);
    }
    red[tid] = m;
    __syncthreads();
    for (int s = 512; s > 0; s >>= 1) {
        if (tid < s) red[tid] = fmaxf(red[tid], red[tid + s]);
        __syncthreads();
    }
    const float M = red[0];
    __syncthreads();
    float e[4];
    float sum = 0.f;
#pragma unroll
    for (int i = 0; i < 4; i++) {
        e[i] = __expf(l[i] - M);
        sum += e[i];
    }
    red[tid] = sum;
    __syncthreads();
    for (int s = 512; s > 0; s >>= 1) {
        if (tid < s) red[tid] += red[tid + s];
        __syncthreads();
    }
    const float inv = 1.f / red[0];
#pragma unroll
    for (int i = 0; i < 4; i++) g_alpha[tid + i * 1024] = e[i] * inv;
}

// ---------------- K4c: out[j] = sum_t alpha[t] * hs[t][j] --------------------
__global__ __launch_bounds__(128) void k_out(float* __restrict__ out) {
    __shared__ float al[T_STEPS];
    const int j = blockIdx.x * 128 + threadIdx.x;
    for (int i = threadIdx.x; i < T_STEPS; i += 128) al[i] = g_alpha[i];
    __syncthreads();
    float acc = 0.f;
#pragma unroll 8
    for (int t = 0; t < T_STEPS; t++)
        acc += al[t] * g_hs[(size_t)t * HD + j];
    out[j] = acc;
}

// ---------------- launch ------------------------------------------------------
extern "C" void kernel_launch(void* const* d_in, const int* in_sizes, int n_in,
                              void* d_out, int out_size) {
    const float* H     = (const float*)d_in[0];
    // d_in[1] = TE (unused)
    const float* X     = (const float*)d_in[2];
    const float* W_ih  = (const float*)d_in[3];
    const float* W_hh  = (const float*)d_in[4];
    const float* b_ih  = (const float*)d_in[5];
    const float* b_hh  = (const float*)d_in[6];
    const float* w_att = (const float*)d_in[7];
    float* out = (float*)d_out;

    k_poison<<<(T_STEPS * HD) / 1024, 1024>>>();
    k_gemm1<<<dim3(32, 8), 256>>>(H, X);
    k_gemm2<<<dim3(32, 24), 256>>>(W_ih, b_ih);
    k_scan<<<SCAN_CTAS, 512>>>(W_hh, b_hh);
    k_logits<<<512, 256>>>(w_att);
    k_softmax<<<1, 1024>>>();
    k_out<<<4, 128>>>(out);
}

// round 17
// speedup vs baseline: 2.0781x; 1.1414x over previous
#include <cuda_runtime.h>
#include <cstdint>

#define T_STEPS 4096
#define HD      512
#define NC      4880
#define G3      1536
#define SCAN_CTAS 64
#define SCAN_WARPS 8    // warps per CTA; SCAN_CTAS*SCAN_WARPS == 512 units
#define SENT 0x7FC00BADu

// packed dual-fp32 FMA (PTX-only instruction; bit-exact 2x fp32 FMA)
#define FMA2(d, a, b, c) \
    asm("fma.rn.f32x2 %0, %1, %2, %3;" : "=l"(d) : "l"(a), "l"(b), "l"(c))

__device__ __forceinline__ float u64lo(unsigned long long v) {
    return __uint_as_float((unsigned)v);
}
__device__ __forceinline__ float u64hi(unsigned long long v) {
    return __uint_as_float((unsigned)(v >> 32));
}

// ---------------- scratch (device globals: no runtime allocation) ------------
__device__ float    g_visit[(size_t)T_STEPS * HD];    // 8 MB
__device__ float    g_gi[(size_t)T_STEPS * G3];       // 25 MB
__device__ float    g_hs[(size_t)T_STEPS * HD];       // 8 MB
__device__ float    g_logits[T_STEPS];
__device__ float    g_alpha[T_STEPS];

// ---------------- K0: poison g_hs with the NaN sentinel ----------------------
__global__ void k_poison() {
    size_t i = (size_t)blockIdx.x * 1024 + threadIdx.x;
    ((unsigned*)g_hs)[i] = SENT;
}

// ---------------- K1: visit_emb[t][j] = sum_c H[c][t] * X[c][j] --------------
__global__ __launch_bounds__(256) void k_gemm1(const float* __restrict__ H,
                                               const float* __restrict__ X) {
    __shared__ float As[16][128];
    __shared__ float Bs[16][64];
    const int t0 = blockIdx.x * 128, j0 = blockIdx.y * 64;
    const int tid = threadIdx.x;
    const int tx = tid & 15, ty = tid >> 4;

    float acc[8][4];
#pragma unroll
    for (int m = 0; m < 8; m++)
#pragma unroll
        for (int n = 0; n < 4; n++) acc[m][n] = 0.f;

    for (int c0 = 0; c0 < NC; c0 += 16) {
#pragma unroll
        for (int i = 0; i < 2; i++) {
            int idx = tid + i * 256;
            int r = idx >> 5, c4 = (idx & 31) << 2;
            *(float4*)&As[r][c4] =
                *(const float4*)&H[(size_t)(c0 + r) * T_STEPS + t0 + c4];
        }
        {
            int r = tid >> 4, c4 = (tid & 15) << 2;
            *(float4*)&Bs[r][c4] =
                *(const float4*)&X[(size_t)(c0 + r) * HD + j0 + c4];
        }
        __syncthreads();
#pragma unroll
        for (int kk = 0; kk < 16; kk++) {
            float4 a0 = *(float4*)&As[kk][ty * 8];
            float4 a1 = *(float4*)&As[kk][ty * 8 + 4];
            float4 b  = *(float4*)&Bs[kk][tx * 4];
            float a[8] = {a0.x, a0.y, a0.z, a0.w, a1.x, a1.y, a1.z, a1.w};
            float bb[4] = {b.x, b.y, b.z, b.w};
#pragma unroll
            for (int m = 0; m < 8; m++)
#pragma unroll
                for (int n = 0; n < 4; n++) acc[m][n] += a[m] * bb[n];
        }
        __syncthreads();
    }
#pragma unroll
    for (int m = 0; m < 8; m++) {
        float4 v = make_float4(acc[m][0], acc[m][1], acc[m][2], acc[m][3]);
        *(float4*)&g_visit[(size_t)(t0 + ty * 8 + m) * HD + j0 + tx * 4] = v;
    }
}

// ---------------- K2: gi[t][g] = sum_k visit[t][k] * W_ih[g][k] + b_ih[g] ----
__global__ __launch_bounds__(256) void k_gemm2(const float* __restrict__ W_ih,
                                               const float* __restrict__ b_ih) {
    __shared__ float As[32][129];   // As[k][t], padded
    __shared__ float Bs[32][64];    // Bs[k][g]
    const int t0 = blockIdx.x * 128, g0 = blockIdx.y * 64;
    const int tid = threadIdx.x;
    const int tx = tid & 15, ty = tid >> 4;

    float acc[8][4];
#pragma unroll
    for (int m = 0; m < 8; m++)
#pragma unroll
        for (int n = 0; n < 4; n++) acc[m][n] = 0.f;

    for (int k0 = 0; k0 < HD; k0 += 32) {
        {
            int t_l = tid >> 1;
#pragma unroll
            for (int i = 0; i < 4; i++) {
                int q = (tid & 1) + i * 2;   // 0..7
                float4 v = *(const float4*)&g_visit[(size_t)(t0 + t_l) * HD + k0 + q * 4];
                As[q * 4 + 0][t_l] = v.x; As[q * 4 + 1][t_l] = v.y;
                As[q * 4 + 2][t_l] = v.z; As[q * 4 + 3][t_l] = v.w;
            }
        }
        {
            int g_l = tid >> 2;
#pragma unroll
            for (int i = 0; i < 2; i++) {
                int q = (tid & 3) + i * 4;   // 0..7
                float4 w = *(const float4*)&W_ih[(size_t)(g0 + g_l) * HD + k0 + q * 4];
                Bs[q * 4 + 0][g_l] = w.x; Bs[q * 4 + 1][g_l] = w.y;
                Bs[q * 4 + 2][g_l] = w.z; Bs[q * 4 + 3][g_l] = w.w;
            }
        }
        __syncthreads();
#pragma unroll
        for (int kk = 0; kk < 32; kk++) {
            float a[8];
#pragma unroll
            for (int m = 0; m < 8; m++) a[m] = As[kk][ty * 8 + m];
            float4 b = *(float4*)&Bs[kk][tx * 4];
            float bb[4] = {b.x, b.y, b.z, b.w};
#pragma unroll
            for (int m = 0; m < 8; m++)
#pragma unroll
                for (int n = 0; n < 4; n++) acc[m][n] += a[m] * bb[n];
        }
        __syncthreads();
    }
    float4 bias = *(const float4*)&b_ih[g0 + tx * 4];
    float bb[4] = {bias.x, bias.y, bias.z, bias.w};
#pragma unroll
    for (int m = 0; m < 8; m++) {
        float4 v = make_float4(acc[m][0] + bb[0], acc[m][1] + bb[1],
                               acc[m][2] + bb[2], acc[m][3] + bb[3]);
        *(float4*)&g_gi[(size_t)(t0 + ty * 8 + m) * G3 + g0 + tx * 4] = v;
    }
}

// ---------------- K3: persistent GRU scan (data-is-the-flag, relaxed atomics)
// 64 CTAs x 256 threads (8 warps = 8 units per CTA): halves the per-SM issue
// work (FMA2/MUFU/SHFL serialization was ~700cyc/step at 16 warps/SM; MUFU
// alone was 96 instr * rt8 / 4SMSP = 192cyc). Protocol unchanged:
//   * each thread polls TWO words of h(t-1) (tid, tid+256) with
//     ld.relaxed.gpu + nanosleep backoff; stages into parity-double-buffered
//     SMEM; ONE bar
//   * conflict-free chunked layout (lane l owns comps i*128+4l..+3), FMA2 dots
//   * lane0 publishes h(t)[j] with ONE st.relaxed.gpu (8 words/CTA = 1 sector)
__global__ __launch_bounds__(256) void k_scan(const float* __restrict__ Whh,
                                              const float* __restrict__ bhh) {
    __shared__ float sh_hin[2][HD];
    const int tid = threadIdx.x;
    const int warp = tid >> 5, lane = tid & 31;
    const int j = blockIdx.x * SCAN_WARPS + warp;

    // weights packed as f32x2 pairs; lane l, chunk i covers comps i*128+4l..+3
    ulonglong2 wr[4], wz[4], wn[4];
#pragma unroll
    for (int i = 0; i < 4; i++) {
        wr[i] = *(const ulonglong2*)&Whh[(size_t)j * HD          + i * 128 + lane * 4];
        wz[i] = *(const ulonglong2*)&Whh[(size_t)(512  + j) * HD + i * 128 + lane * 4];
        wn[i] = *(const ulonglong2*)&Whh[(size_t)(1024 + j) * HD + i * 128 + lane * 4];
    }
    const float br = bhh[j], bz = bhh[512 + j], bn = bhh[1024 + j];
    float h_prev = 0.f;

    for (int t = 0; t < T_STEPS; t++) {
        // prefetch gate inputs (independent of h)
        const float* gp = &g_gi[(size_t)t * G3];
        float ir  = __ldg(gp + j);
        float iz  = __ldg(gp + 512 + j);
        float in_ = __ldg(gp + 1024 + j);

        float accr = 0.f, accz = 0.f, accn = 0.f;
        if (t > 0) {
            // poll own TWO words of h(t-1); relaxed loads, nanosleep backoff
            const float* src = &g_hs[(size_t)(t - 1) * HD + tid];
            unsigned u0, u1;
            asm volatile("ld.relaxed.gpu.global.b32 %0, [%1];"
                         : "=r"(u0) : "l"(src) : "memory");
            asm volatile("ld.relaxed.gpu.global.b32 %0, [%1];"
                         : "=r"(u1) : "l"(src + 256) : "memory");
            while (u0 == SENT || u1 == SENT) {
                __nanosleep(64);
                asm volatile("ld.relaxed.gpu.global.b32 %0, [%1];"
                             : "=r"(u0) : "l"(src) : "memory");
                asm volatile("ld.relaxed.gpu.global.b32 %0, [%1];"
                             : "=r"(u1) : "l"(src + 256) : "memory");
            }
            sh_hin[t & 1][tid]       = __uint_as_float(u0);
            sh_hin[t & 1][tid + 256] = __uint_as_float(u1);
            __syncthreads();

            unsigned long long ar0 = 0, ar1 = 0, az0 = 0, az1 = 0, an0 = 0, an1 = 0;
#pragma unroll
            for (int i = 0; i < 4; i++) {
                ulonglong2 h2 = *(const ulonglong2*)&sh_hin[t & 1][i * 128 + lane * 4];
                FMA2(ar0, wr[i].x, h2.x, ar0);
                FMA2(ar1, wr[i].y, h2.y, ar1);
                FMA2(az0, wz[i].x, h2.x, az0);
                FMA2(az1, wz[i].y, h2.y, az1);
                FMA2(an0, wn[i].x, h2.x, an0);
                FMA2(an1, wn[i].y, h2.y, an1);
            }
            accr = (u64lo(ar0) + u64hi(ar0)) + (u64lo(ar1) + u64hi(ar1));
            accz = (u64lo(az0) + u64hi(az0)) + (u64lo(az1) + u64hi(az1));
            accn = (u64lo(an0) + u64hi(an0)) + (u64lo(an1) + u64hi(an1));
        }
#pragma unroll
        for (int off = 16; off > 0; off >>= 1) {
            accr += __shfl_xor_sync(0xffffffffu, accr, off);
            accz += __shfl_xor_sync(0xffffffffu, accz, off);
            accn += __shfl_xor_sync(0xffffffffu, accn, off);
        }
        float r = 1.f / (1.f + __expf(-(ir + accr + br)));
        float z = 1.f / (1.f + __expf(-(iz + accz + bz)));
        // tanh(x) = 2*sigmoid(2x) - 1 (EX2+RCP chain, shorter than tanhf)
        float nx = in_ + r * (accn + bn);
        float n = __fmaf_rn(2.f, 1.f / (1.f + __expf(-2.f * nx)), -1.f);
        float hn = (1.f - z) * n + z * h_prev;
        h_prev = hn;

        if (lane == 0) {
            asm volatile("st.relaxed.gpu.global.b32 [%0], %1;"
                         :: "l"(&g_hs[(size_t)t * HD + j]),
                            "r"(__float_as_uint(hn)) : "memory");
        }
    }
}

// ---------------- K4a: logits[t] = dot(hs[t], w_att) -------------------------
__global__ __launch_bounds__(256) void k_logits(const float* __restrict__ watt) {
    const int warp = threadIdx.x >> 5, lane = threadIdx.x & 31;
    const int t = blockIdx.x * 8 + warp;
    float acc = 0.f;
#pragma unroll
    for (int i = 0; i < 4; i++) {
        float4 h4 = *(const float4*)&g_hs[(size_t)t * HD + lane * 16 + i * 4];
        float4 w4 = *(const float4*)&watt[lane * 16 + i * 4];
        acc += h4.x * w4.x + h4.y * w4.y + h4.z * w4.z + h4.w * w4.w;
    }
#pragma unroll
    for (int off = 16; off > 0; off >>= 1)
        acc += __shfl_xor_sync(0xffffffffu, acc, off);
    if (lane == 0) g_logits[t] = acc;
}

// ---------------- K4b: softmax over 4096 logits ------------------------------
__global__ __launch_bounds__(1024) void k_softmax() {
    __shared__ float red[1024];
    const int tid = threadIdx.x;
    float l[4];
    float m = -3.4e38f;
#pragma unroll
    for (int i = 0; i < 4; i++) {
        l[i] = g_logits[tid + i * 1024];
        m = fmaxf(m, l[i]);
    }
    red[tid] = m;
    __syncthreads();
    for (int s = 512; s > 0; s >>= 1) {
        if (tid < s) red[tid] = fmaxf(red[tid], red[tid + s]);
        __syncthreads();
    }
    const float M = red[0];
    __syncthreads();
    float e[4];
    float sum = 0.f;
#pragma unroll
    for (int i = 0; i < 4; i++) {
        e[i] = __expf(l[i] - M);
        sum += e[i];
    }
    red[tid] = sum;
    __syncthreads();
    for (int s = 512; s > 0; s >>= 1) {
        if (tid < s) red[tid] += red[tid + s];
        __syncthreads();
    }
    const float inv = 1.f / red[0];
#pragma unroll
    for (int i = 0; i < 4; i++) g_alpha[tid + i * 1024] = e[i] * inv;
}

// ---------------- K4c: out[j] = sum_t alpha[t] * hs[t][j] --------------------
__global__ __launch_bounds__(128) void k_out(float* __restrict__ out) {
    __shared__ float al[T_STEPS];
    const int j = blockIdx.x * 128 + threadIdx.x;
    for (int i = threadIdx.x; i < T_STEPS; i += 128) al[i] = g_alpha[i];
    __syncthreads();
    float acc = 0.f;
#pragma unroll 8
    for (int t = 0; t < T_STEPS; t++)
        acc += al[t] * g_hs[(size_t)t * HD + j];
    out[j] = acc;
}

// ---------------- launch ------------------------------------------------------
extern "C" void kernel_launch(void* const* d_in, const int* in_sizes, int n_in,
                              void* d_out, int out_size) {
    const float* H     = (const float*)d_in[0];
    // d_in[1] = TE (unused)
    const float* X     = (const float*)d_in[2];
    const float* W_ih  = (const float*)d_in[3];
    const float* W_hh  = (const float*)d_in[4];
    const float* b_ih  = (const float*)d_in[5];
    const float* b_hh  = (const float*)d_in[6];
    const float* w_att = (const float*)d_in[7];
    float* out = (float*)d_out;

    k_poison<<<(T_STEPS * HD) / 1024, 1024>>>();
    k_gemm1<<<dim3(32, 8), 256>>>(H, X);
    k_gemm2<<<dim3(32, 24), 256>>>(W_ih, b_ih);
    k_scan<<<SCAN_CTAS, 256>>>(W_hh, b_hh);
    k_logits<<<512, 256>>>(w_att);
    k_softmax<<<1, 1024>>>();
    k_out<<<4, 128>>>(out);
}